// round 16
// baseline (speedup 1.0000x reference)
#include <cuda_runtime.h>
#include <cuda_bf16.h>

#define BB 4
#define CC 256
#define NHEAD 8
#define DK 32
#define NN 1024
#define SK 64            // keys per chunk
#define CPS 16           // chunks per stream (1024/64)

typedef unsigned int u32;
typedef unsigned short u16;

// ---------------- scratch ----------------
__device__ u16   g_Q16[BB * CC * NN];           // Q fp16
__device__ u16   g_K16[BB * 3 * CC * NN];       // K fp16
__device__ u16   g_V16[BB * 3 * CC * NN];       // V fp16
__device__ float g_part[BB * 3 * CC * NN];      // per-stream unnormalized O
__device__ float g_ssum[BB * 3 * NHEAD * NN];   // per-stream softmax sums
__device__ __align__(16) u16 g_Xh[BB * CC * NN];  // combined attn out, bf16 hi
__device__ __align__(16) u16 g_Xl[BB * CC * NN];  // combined attn out, bf16 lo
// pre-converted operands
__device__ __align__(16) u16 g_WK[CC * CC];       // Wk fp16
__device__ __align__(16) u16 g_WV[CC * CC];       // Wv fp16
__device__ __align__(16) u16 g_WQ[CC * CC];       // Wq fp16
__device__ __align__(16) u16 g_WOh[CC * CC];      // Wo bf16 hi
__device__ __align__(16) u16 g_WOl[CC * CC];      // Wo bf16 lo
__device__ __align__(16) u16 g_Xin[BB * 3 * CC * NN];  // gamma-scaled inputs fp16

// ---------------- helpers ----------------
__device__ __forceinline__ u32 smem_u32(const void* p) {
    u32 a;
    asm("{ .reg .u64 t; cvta.to.shared.u64 t, %1; cvt.u32.u64 %0, t; }" : "=r"(a) : "l"(p));
    return a;
}
__device__ __forceinline__ u32 cvt_bf16x2(float hi, float lo) {
    u32 r;
    asm("cvt.rn.bf16x2.f32 %0, %1, %2;" : "=r"(r) : "f"(hi), "f"(lo));
    return r;
}
__device__ __forceinline__ u32 cvt_f16x2(float hi, float lo) {
    u32 r;
    asm("cvt.rn.f16x2.f32 %0, %1, %2;" : "=r"(r) : "f"(hi), "f"(lo));
    return r;
}
__device__ __forceinline__ u32 ex2_f16x2(u32 t) {
    u32 r;
    asm("ex2.approx.f16x2 %0, %1;" : "=r"(r) : "r"(t));
    return r;
}
__device__ __forceinline__ float bf16bits_f(u16 v) {
    return __uint_as_float(((u32)v) << 16);
}
__device__ __forceinline__ void split2(float a, float b, u32& h, u32& l) {
    h = cvt_bf16x2(b, a);
    float la = a - bf16bits_f((u16)h);
    float lb = b - bf16bits_f((u16)(h >> 16));
    l = cvt_bf16x2(lb, la);
}

#define LDSM4(R, a) \
    asm volatile("ldmatrix.sync.aligned.m8n8.x4.shared.b16 {%0,%1,%2,%3}, [%4];" \
        : "=r"((R)[0]), "=r"((R)[1]), "=r"((R)[2]), "=r"((R)[3]) : "r"(a))
#define LDSM4T(R, a) \
    asm volatile("ldmatrix.sync.aligned.m8n8.x4.trans.shared.b16 {%0,%1,%2,%3}, [%4];" \
        : "=r"((R)[0]), "=r"((R)[1]), "=r"((R)[2]), "=r"((R)[3]) : "r"(a))

#define MMA(C, A, b0, b1) \
    asm volatile("mma.sync.aligned.m16n8k16.row.col.f32.bf16.bf16.f32 " \
        "{%0,%1,%2,%3}, {%4,%5,%6,%7}, {%8,%9}, {%0,%1,%2,%3};" \
        : "+f"((C)[0]), "+f"((C)[1]), "+f"((C)[2]), "+f"((C)[3]) \
        : "r"((A)[0]), "r"((A)[1]), "r"((A)[2]), "r"((A)[3]), "r"(b0), "r"(b1))

#define MMAH(C, A, b0, b1) \
    asm volatile("mma.sync.aligned.m16n8k16.row.col.f32.f16.f16.f32 " \
        "{%0,%1,%2,%3}, {%4,%5,%6,%7}, {%8,%9}, {%0,%1,%2,%3};" \
        : "+f"((C)[0]), "+f"((C)[1]), "+f"((C)[2]), "+f"((C)[3]) \
        : "r"((A)[0]), "r"((A)[1]), "r"((A)[2]), "r"((A)[3]), "r"(b0), "r"(b1))

#define WTR 40
#define XTR 72

// ---------------- prep: convert all GEMM operands once ---------------------
// t ranges: [0,49152)        Wk/Wv/Wq -> fp16      (3 x 16384 float4s)
//           [49152,65536)    Wo -> bf16 hi/lo      (16384 float4s)
//           [65536,851968)   X (12 planes) -> gamma-scaled fp16
#define PREP_THREADS (851968)

__global__ __launch_bounds__(256)
void prep_kernel(const float* __restrict__ Wk_, const float* __restrict__ Wv_,
                 const float* __restrict__ Wq_, const float* __restrict__ Wo_,
                 const float* __restrict__ x0,
                 const float* __restrict__ x1,
                 const float* __restrict__ x2,
                 const float* __restrict__ g0p,
                 const float* __restrict__ g1p,
                 const float* __restrict__ g2p)
{
    int t = blockIdx.x * 256 + threadIdx.x;
    if (t < 49152) {
        int wi = t / 16384;
        int e  = (t - wi * 16384) * 4;
        const float* W = (wi == 0) ? Wk_ : ((wi == 1) ? Wv_ : Wq_);
        u16* D = (wi == 0) ? g_WK : ((wi == 1) ? g_WV : g_WQ);
        float4 v = *(const float4*)&W[e];
        *(uint2*)(D + e) = make_uint2(cvt_f16x2(v.y, v.x), cvt_f16x2(v.w, v.z));
    } else if (t < 65536) {
        int e = (t - 49152) * 4;
        float4 v = *(const float4*)&Wo_[e];
        u32 h01, l01, h23, l23;
        split2(v.x, v.y, h01, l01);
        split2(v.z, v.w, h23, l23);
        *(uint2*)(g_WOh + e) = make_uint2(h01, h23);
        *(uint2*)(g_WOl + e) = make_uint2(l01, l23);
    } else {
        int u = t - 65536;
        int tile = u >> 16;              // 0..11  (b*3+s)
        int e    = (u & 65535) * 4;
        int s = tile % 3;
        const float* xb = (s == 0) ? x0 : ((s == 1) ? x1 : x2);
        const float* gp = (s == 0) ? g0p : ((s == 1) ? g1p : g2p);
        float gamma = gp[0];
        int b = tile / 3;
        float4 v = *(const float4*)&xb[(size_t)b * CC * NN + e];
        v.x *= gamma; v.y *= gamma; v.z *= gamma; v.w *= gamma;
        *(uint2*)(g_Xin + (size_t)tile * CC * NN + e) =
            make_uint2(cvt_f16x2(v.y, v.x), cvt_f16x2(v.w, v.z));
    }
}

// ---------------- projection: one output matrix per block, fp16 inputs -----
// z = b*7 + job; jobs: 0:K s0, 1:V s0, 2:Q s0, 3:K s1, 4:V s1, 5:K s2, 6:V s2
__global__ __launch_bounds__(128)
void proj_one(const float* __restrict__ bk_,
              const float* __restrict__ bv_,
              const float* __restrict__ bq_,
              u16* __restrict__ K16,
              u16* __restrict__ V16,
              u16* __restrict__ Q16)
{
    __shared__ __align__(16) u16 sW[64 * WTR];
    __shared__ __align__(16) u16 sX[32 * XTR];

    const int bz  = blockIdx.z;
    const int b   = bz / 7;
    const int job = bz - b * 7;
    const int s   = (job < 3) ? 0 : ((job < 5) ? 1 : 2);
    const int typ = (job == 2) ? 2 : ((job == 0 || job == 3 || job == 5) ? 0 : 1);

    const u16* Wm = (typ == 0) ? g_WK : ((typ == 1) ? g_WV : g_WQ);
    const float* bias = (typ == 0) ? bk_ : ((typ == 1) ? bv_ : bq_);
    u16* Y = (typ == 0) ? (K16 + (size_t)(b * 3 + s) * CC * NN)
           : (typ == 1) ? (V16 + (size_t)(b * 3 + s) * CC * NN)
                        : (Q16 + (size_t)b * CC * NN);
    const u16* X = g_Xin + (size_t)(b * 3 + s) * CC * NN;

    const int o0 = blockIdx.y * 64;
    const int n0 = blockIdx.x * 64;
    const int tid  = threadIdx.x;
    const int w    = tid >> 5;
    const int lane = tid & 31;
    const int lr   = lane & 7;
    const int oct  = lane >> 3;
    const int g    = lane >> 2;
    const int t4   = lane & 3;

    const u32 bW = smem_u32(sW);
    const u32 bX = smem_u32(sX);

    // tile fill mapping: 256 uint4 per tile per operand, 2 per thread
    int wm[2], wc[2], xk[2], xn[2];
    #pragma unroll
    for (int j = 0; j < 2; j++) {
        int i = tid + j * 128;
        wm[j] = i >> 2;  wc[j] = (i & 3) * 8;
        xk[j] = i >> 3;  xn[j] = (i & 7) * 8;
    }

    // register prefetch of first k-tile
    uint4 wr[2], xr[2];
    #pragma unroll
    for (int j = 0; j < 2; j++) {
        wr[j] = *(const uint4*)&Wm[(size_t)(o0 + wm[j]) * CC + wc[j]];
        xr[j] = *(const uint4*)&X[(size_t)xk[j] * NN + n0 + xn[j]];
    }

    float C[8][4] = {};

    for (int kb = 0; kb < CC; kb += 32) {
        if (kb) __syncthreads();
        #pragma unroll
        for (int j = 0; j < 2; j++) {
            *(uint4*)&sW[wm[j] * WTR + wc[j]] = wr[j];
            *(uint4*)&sX[xk[j] * XTR + xn[j]] = xr[j];
        }
        __syncthreads();

        if (kb + 32 < CC) {
            #pragma unroll
            for (int j = 0; j < 2; j++) {
                wr[j] = *(const uint4*)&Wm[(size_t)(o0 + wm[j]) * CC + kb + 32 + wc[j]];
                xr[j] = *(const uint4*)&X[(size_t)(kb + 32 + xk[j]) * NN + n0 + xn[j]];
            }
        }

        #pragma unroll
        for (int kt = 0; kt < 2; kt++) {
            u32 aoff = (u32)(((w * 16 + (oct & 1) * 8 + lr) * WTR + kt * 16 + (oct >> 1) * 8) * 2);
            u32 aa[4];
            LDSM4(aa, bW + aoff);
            #pragma unroll
            for (int nt = 0; nt < 4; nt++) {
                u32 boff = (u32)(((kt * 16 + (oct & 1) * 8 + lr) * XTR + nt * 16 + (oct >> 1) * 8) * 2);
                u32 bx[4];
                LDSM4T(bx, bX + boff);
                MMAH(C[2 * nt],     aa, bx[0], bx[1]);
                MMAH(C[2 * nt + 1], aa, bx[2], bx[3]);
            }
        }
    }

    const int or0 = o0 + w * 16 + g;
    const int or1 = or0 + 8;
    const float b0v = bias[or0], b1v = bias[or1];
    #pragma unroll
    for (int j = 0; j < 8; j++) {
        int ne = n0 + (j >> 1) * 16 + (j & 1) * 8 + 2 * t4;
        size_t i0 = (size_t)or0 * NN + ne;
        size_t i1 = (size_t)or1 * NN + ne;
        *(u32*)(Y + i0) = cvt_f16x2(C[j][1] + b0v, C[j][0] + b0v);
        *(u32*)(Y + i1) = cvt_f16x2(C[j][3] + b1v, C[j][2] + b1v);
    }
}

// ---------------- combine: 3 stream partials -> normalized bf16 hi/lo ------
__global__ __launch_bounds__(256)
void combine_kernel()
{
    const int nvec = NN / 4;
    int t = blockIdx.x * 256 + threadIdx.x;      // over BB*CC*nvec
    int n0 = (t % nvec) * 4;
    int c  = (t / nvec) % CC;
    int b  = t / (nvec * CC);
    int h  = c / DK;

    size_t eo = ((size_t)(b * 3) * CC + c) * NN + n0;
    float4 p0 = *(const float4*)&g_part[eo];
    float4 p1 = *(const float4*)&g_part[eo + (size_t)CC * NN];
    float4 p2 = *(const float4*)&g_part[eo + (size_t)2 * CC * NN];
    size_t so = ((size_t)(b * 3) * NHEAD + h) * NN + n0;
    float4 s0 = *(const float4*)&g_ssum[so];
    float4 s1 = *(const float4*)&g_ssum[so + (size_t)NHEAD * NN];
    float4 s2 = *(const float4*)&g_ssum[so + (size_t)2 * NHEAD * NN];

    float4 xv;
    xv.x = __fdividef(p0.x + p1.x + p2.x, s0.x + s1.x + s2.x);
    xv.y = __fdividef(p0.y + p1.y + p2.y, s0.y + s1.y + s2.y);
    xv.z = __fdividef(p0.z + p1.z + p2.z, s0.z + s1.z + s2.z);
    xv.w = __fdividef(p0.w + p1.w + p2.w, s0.w + s1.w + s2.w);

    u32 h01, l01, h23, l23;
    split2(xv.x, xv.y, h01, l01);
    split2(xv.z, xv.w, h23, l23);
    size_t di = ((size_t)b * CC + c) * NN + n0;
    *(uint2*)(g_Xh + di) = make_uint2(h01, h23);
    *(uint2*)(g_Xl + di) = make_uint2(l01, l23);
}

// ---------------- Wo projection: 64o x 32n tiles, pre-split W --------------
#define XTR2 40

__global__ __launch_bounds__(128)
void proj_wo(const float* __restrict__ bias,
             float* __restrict__ Yf)
{
    __shared__ __align__(16) u16 sWh[64 * WTR], sWl[64 * WTR];
    __shared__ __align__(16) u16 sXh[32 * XTR2], sXl[32 * XTR2];

    const int b  = blockIdx.z;
    const int o0 = blockIdx.y * 64;
    const int n0 = blockIdx.x * 32;
    const int tid  = threadIdx.x;
    const int w    = tid >> 5;
    const int lane = tid & 31;
    const int lr   = lane & 7;
    const int oct  = lane >> 3;
    const int g    = lane >> 2;
    const int t4   = lane & 3;

    const u16* Xh = g_Xh + (size_t)b * CC * NN;
    const u16* Xl = g_Xl + (size_t)b * CC * NN;

    const u32 bWh = smem_u32(sWh), bWl = smem_u32(sWl);
    const u32 bXh = smem_u32(sXh), bXl = smem_u32(sXl);

    // W tile: 64 rows x 32 cols = 256 uint4 per array, 2/thread
    int wm[2], wc[2], xk[2], xn[2];
    #pragma unroll
    for (int j = 0; j < 2; j++) {
        int i = tid + j * 128;
        wm[j] = i >> 2;  wc[j] = (i & 3) * 8;
        xk[j] = i >> 3;  xn[j] = (i & 7) * 4;   // X tile: 32x32, uint2 (4 elems)
    }

    uint4 whr[2], wlr[2];
    uint2 xhr[2], xlr[2];
    #pragma unroll
    for (int j = 0; j < 2; j++) {
        size_t wo = (size_t)(o0 + wm[j]) * CC + wc[j];
        whr[j] = *(const uint4*)&g_WOh[wo];
        wlr[j] = *(const uint4*)&g_WOl[wo];
        size_t xo = (size_t)xk[j] * NN + n0 + xn[j];
        xhr[j] = *(const uint2*)(Xh + xo);
        xlr[j] = *(const uint2*)(Xl + xo);
    }

    float Cacc[4][4] = {};

    for (int kb = 0; kb < CC; kb += 32) {
        if (kb) __syncthreads();
        #pragma unroll
        for (int j = 0; j < 2; j++) {
            *(uint4*)&sWh[wm[j] * WTR + wc[j]] = whr[j];
            *(uint4*)&sWl[wm[j] * WTR + wc[j]] = wlr[j];
            *(uint2*)&sXh[xk[j] * XTR2 + xn[j]] = xhr[j];
            *(uint2*)&sXl[xk[j] * XTR2 + xn[j]] = xlr[j];
        }
        __syncthreads();

        if (kb + 32 < CC) {
            #pragma unroll
            for (int j = 0; j < 2; j++) {
                size_t wo = (size_t)(o0 + wm[j]) * CC + kb + 32 + wc[j];
                whr[j] = *(const uint4*)&g_WOh[wo];
                wlr[j] = *(const uint4*)&g_WOl[wo];
                size_t xo = (size_t)(kb + 32 + xk[j]) * NN + n0 + xn[j];
                xhr[j] = *(const uint2*)(Xh + xo);
                xlr[j] = *(const uint2*)(Xl + xo);
            }
        }

        #pragma unroll
        for (int kt = 0; kt < 2; kt++) {
            u32 ah[4], al[4];
            u32 aoff = (u32)(((w * 16 + (oct & 1) * 8 + lr) * WTR + kt * 16 + (oct >> 1) * 8) * 2);
            LDSM4(ah, bWh + aoff);
            LDSM4(al, bWl + aoff);
            #pragma unroll
            for (int nt = 0; nt < 2; nt++) {
                u32 boff = (u32)(((kt * 16 + (oct & 1) * 8 + lr) * XTR2 + nt * 16 + (oct >> 1) * 8) * 2);
                u32 bh[4], bl[4];
                LDSM4T(bh, bXh + boff);
                LDSM4T(bl, bXl + boff);
                MMA(Cacc[2 * nt],     ah, bh[0], bh[1]);
                MMA(Cacc[2 * nt],     al, bh[0], bh[1]);
                MMA(Cacc[2 * nt],     ah, bl[0], bl[1]);
                MMA(Cacc[2 * nt + 1], ah, bh[2], bh[3]);
                MMA(Cacc[2 * nt + 1], al, bh[2], bh[3]);
                MMA(Cacc[2 * nt + 1], ah, bl[2], bl[3]);
            }
        }
    }

    const int or0 = o0 + w * 16 + g;
    const int or1 = or0 + 8;
    const float bv0 = bias[or0], bv1 = bias[or1];
    #pragma unroll
    for (int j = 0; j < 4; j++) {
        int ne = n0 + (j >> 1) * 16 + (j & 1) * 8 + 2 * t4;
        size_t i0 = (size_t)(b * CC + or0) * NN + ne;
        size_t i1 = (size_t)(b * CC + or1) * NN + ne;
        *(float2*)&Yf[i0] = make_float2(Cacc[j][0] + bv0, Cacc[j][1] + bv0);
        *(float2*)&Yf[i1] = make_float2(Cacc[j][2] + bv1, Cacc[j][3] + bv1);
    }
}

// ---------------- mma.sync attention: split-KV, ex2.f16x2, ones-col ssum ---
#define TROW 72
#define VROWS 48        // 32 data rows + ones row (32) + zero rows (33..47)

__global__ __launch_bounds__(128, 5)
void attn_mma_kernel()
{
    __shared__ __align__(16) u16 sQ[DK * TROW];
    __shared__ __align__(16) u16 sK[2][DK * TROW];
    __shared__ __align__(16) u16 sV[2][VROWS * TROW];

    const int tid  = threadIdx.x;
    const int w    = tid >> 5;
    const int lane = tid & 31;
    const int lr   = lane & 7;
    const int oct  = lane >> 3;
    const int g    = lane >> 2;
    const int t4   = lane & 3;

    const int bz = blockIdx.z;      // 0..11
    const int b  = bz / 3;
    const int s  = bz - b * 3;      // stream
    const int hh = blockIdx.y;
    const int q0 = blockIdx.x * 64;
    const int qw = w * 16;

    const size_t kvbase = ((size_t)(b * 3 + s) * CC + hh * DK) * NN;
    const u16* Kg = g_K16 + kvbase;
    const u16* Vg = g_V16 + kvbase;

    int prow[2], pcol[2];
    #pragma unroll
    for (int j = 0; j < 2; j++) {
        int i = tid + j * 128;
        prow[j] = i >> 3;
        pcol[j] = (i & 7) * 8;
    }

    // init V rows 32..47 (row 32 = 1.0h for the ssum column, rest 0), both bufs
    for (int i = tid; i < 16 * TROW; i += 128) {
        int r = 32 + i / TROW;
        int cp = i % TROW;
        u16 val = (r == 32) ? (u16)0x3C00 : (u16)0;
        sV[0][r * TROW + cp] = val;
        sV[1][r * TROW + cp] = val;
    }

    // chunk 0 -> buf0 (direct), prefetch chunk 1 into regs
    uint4 pK[2], pV[2];
    #pragma unroll
    for (int j = 0; j < 2; j++) {
        size_t go = (size_t)prow[j] * NN + pcol[j];
        uint4 k0 = *(const uint4*)&Kg[go];
        uint4 v0 = *(const uint4*)&Vg[go];
        u32 so = prow[j] * TROW + pcol[j];
        *(uint4*)&sK[0][so] = k0;
        *(uint4*)&sV[0][so] = v0;
        pK[j] = *(const uint4*)&Kg[go + SK];
        pV[j] = *(const uint4*)&Vg[go + SK];
    }
    // Q tile
    {
        const u16* srcQ = g_Q16 + ((size_t)b * CC + hh * DK) * NN + q0;
        #pragma unroll
        for (int j = 0; j < 2; j++) {
            size_t go = (size_t)prow[j] * NN + pcol[j];
            *(uint4*)&sQ[prow[j] * TROW + pcol[j]] = *(const uint4*)&srcQ[go];
        }
    }
    __syncthreads();

    u32 qa[2][4];
    {
        const u32 dOff = (oct >> 1) * 8;
        const u32 qOff = (oct & 1) * 8;
        #pragma unroll
        for (int kt = 0; kt < 2; kt++) {
            u32 off = (u32)(((kt * 16 + dOff + lr) * TROW + qw + qOff) * 2);
            LDSM4T(qa[kt], smem_u32(sQ) + off);
        }
    }

    float Ofr[5][4] = {};   // [4] = ones-column ntile: ssum in fp32, MMA-reduced
    const float SC2 = 0.25503483f;   // log2(e) / sqrt(32)

    for (int chunk = 0; chunk < CPS; chunk++) {
        const int cur = chunk & 1;
        const u32 baseK = smem_u32(sK[cur]);
        const u32 baseV = smem_u32(sV[cur]);

        // stage next chunk into the other buffer (overlaps with MMAs below)
        if (chunk + 1 < CPS) {
            #pragma unroll
            for (int j = 0; j < 2; j++) {
                u32 so = prow[j] * TROW + pcol[j];
                *(uint4*)&sK[cur ^ 1][so] = pK[j];
                *(uint4*)&sV[cur ^ 1][so] = pV[j];
            }
        }
        if (chunk + 2 < CPS) {
            const int k2 = (chunk + 2) * SK;
            #pragma unroll
            for (int j = 0; j < 2; j++) {
                size_t go = (size_t)prow[j] * NN + k2 + pcol[j];
                pK[j] = *(const uint4*)&Kg[go];
                pV[j] = *(const uint4*)&Vg[go];
            }
        }

        // ---- S = Q K^T (single fp16) ----
        float S[8][4] = {};
        {
            const u32 dOff   = (oct & 1) * 8;
            const u32 keyOff = (oct >> 1) * 8;
            #pragma unroll
            for (int np = 0; np < 4; np++) {
                #pragma unroll
                for (int kt = 0; kt < 2; kt++) {
                    u32 off = (u32)(((kt * 16 + dOff + lr) * TROW + np * 16 + keyOff) * 2);
                    u32 bv[4];
                    LDSM4T(bv, baseK + off);
                    MMAH(S[2 * np],     qa[kt], bv[0], bv[1]);
                    MMAH(S[2 * np + 1], qa[kt], bv[2], bv[3]);
                }
            }
        }

        // ---- softmax: p = 2^(s*SC2), ex2.approx.f16x2, zero shift ----
        u32 pa[4][4];
        #pragma unroll
        for (int nt = 0; nt < 8; nt++) {
            float t0 = S[nt][0] * SC2;
            float t1 = S[nt][1] * SC2;
            float t2 = S[nt][2] * SC2;
            float t3 = S[nt][3] * SC2;
            int kt = nt >> 1;
            int r  = (nt & 1) * 2;
            pa[kt][r]     = ex2_f16x2(cvt_f16x2(t1, t0));
            pa[kt][r + 1] = ex2_f16x2(cvt_f16x2(t3, t2));
        }

        // ---- O += P V ; ssum via ones column (d=32) ----
        {
            const u32 dOff   = (oct >> 1) * 8;
            const u32 keyOff = (oct & 1) * 8;
            #pragma unroll
            for (int kt = 0; kt < 4; kt++) {
                #pragma unroll
                for (int dp = 0; dp < 2; dp++) {
                    u32 off = (u32)(((dp * 16 + dOff + lr) * TROW + kt * 16 + keyOff) * 2);
                    u32 vv[4];
                    LDSM4(vv, baseV + off);
                    MMAH(Ofr[2 * dp],     pa[kt], vv[0], vv[1]);
                    MMAH(Ofr[2 * dp + 1], pa[kt], vv[2], vv[3]);
                }
                u32 off1 = (u32)(((32 + dOff + lr) * TROW + kt * 16 + keyOff) * 2);
                u32 vv1[4];
                LDSM4(vv1, baseV + off1);
                MMAH(Ofr[4], pa[kt], vv1[0], vv1[1]);
            }
        }
        __syncthreads();   // all reads of buf[cur] done; buf[cur^1] stores visible
    }

    // ---- store unnormalized partials + exact MMA-reduced softmax sums ----
    const size_t obase = kvbase;
    const int qg = q0 + qw + g;
    #pragma unroll
    for (int nt = 0; nt < 4; nt++) {
        int d0 = nt * 8 + 2 * t4;
        g_part[obase + (size_t)d0 * NN + qg]           = Ofr[nt][0];
        g_part[obase + (size_t)(d0 + 1) * NN + qg]     = Ofr[nt][1];
        g_part[obase + (size_t)d0 * NN + qg + 8]       = Ofr[nt][2];
        g_part[obase + (size_t)(d0 + 1) * NN + qg + 8] = Ofr[nt][3];
    }
    if (t4 == 0) {
        size_t sb = ((size_t)(b * 3 + s) * NHEAD + hh) * NN;
        g_ssum[sb + qg]     = Ofr[4][0];   // col 32 (ones) = row sum, row qg
        g_ssum[sb + qg + 8] = Ofr[4][2];   // row qg+8
    }
}

// ---------------- launch --------------------------------------------------
extern "C" void kernel_launch(void* const* d_in, const int* in_sizes, int n_in,
                              void* d_out, int out_size)
{
    const float* x0 = (const float*)d_in[0];
    const float* x1 = (const float*)d_in[1];
    const float* x2 = (const float*)d_in[2];
    const float* g0 = (const float*)d_in[3];
    const float* g1 = (const float*)d_in[4];
    const float* g2 = (const float*)d_in[5];
    const float* Wq = (const float*)d_in[6];
    const float* bq = (const float*)d_in[7];
    const float* Wk = (const float*)d_in[8];
    const float* bk = (const float*)d_in[9];
    const float* Wv = (const float*)d_in[10];
    const float* bv = (const float*)d_in[11];
    const float* Wo = (const float*)d_in[12];
    const float* bo = (const float*)d_in[13];
    float* out = (float*)d_out;

    u16 *Q16, *K16, *V16;
    cudaGetSymbolAddress((void**)&Q16, g_Q16);
    cudaGetSymbolAddress((void**)&K16, g_K16);
    cudaGetSymbolAddress((void**)&V16, g_V16);

    dim3 blk(128);

    // convert all GEMM operands once (W -> fp16 / bf16 hi-lo, X -> fp16*gamma)
    prep_kernel<<<PREP_THREADS / 256, 256>>>(Wk, Wv, Wq, Wo,
                                             x0, x1, x2, g0, g1, g2);

    // projections: one output matrix per block, pure-copy fp16 tiles
    dim3 gridP(NN / 64, CC / 64, BB * 7);
    proj_one<<<gridP, blk>>>(bk, bv, bq, K16, V16, Q16);

    dim3 agrid(NN / 64, NHEAD, BB * 3);
    attn_mma_kernel<<<agrid, blk>>>();

    // combine 3 stream partials -> normalized attn out as bf16 hi/lo
    combine_kernel<<<BB * CC * (NN / 4) / 256, 256>>>();

    // final projection: 64x32 tiles, pre-split Wo
    dim3 gridWo(NN / 32, CC / 64, BB);
    proj_wo<<<gridWo, blk>>>(bo, out);
}

// round 17
// speedup vs baseline: 1.0660x; 1.0660x over previous
#include <cuda_runtime.h>
#include <cuda_bf16.h>

#define BB 4
#define CC 256
#define NHEAD 8
#define DK 32
#define NN 1024
#define SK 64            // keys per chunk
#define CPS 16           // chunks per stream (1024/64)

typedef unsigned int u32;
typedef unsigned short u16;

// ---------------- scratch ----------------
__device__ u16   g_Q16[BB * CC * NN];           // Q fp16
__device__ u16   g_K16[BB * 3 * CC * NN];       // K fp16
__device__ u16   g_V16[BB * 3 * CC * NN];       // V fp16
__device__ float g_part[BB * 3 * CC * NN];      // per-stream unnormalized O
__device__ float g_ssum[BB * 3 * NHEAD * NN];   // per-stream softmax sums
__device__ __align__(16) u16 g_Xh[BB * CC * NN];  // combined attn out, bf16 hi
__device__ __align__(16) u16 g_Xl[BB * CC * NN];  // combined attn out, bf16 lo

// ---------------- helpers ----------------
__device__ __forceinline__ u32 smem_u32(const void* p) {
    u32 a;
    asm("{ .reg .u64 t; cvta.to.shared.u64 t, %1; cvt.u32.u64 %0, t; }" : "=r"(a) : "l"(p));
    return a;
}
__device__ __forceinline__ u32 cvt_bf16x2(float hi, float lo) {
    u32 r;
    asm("cvt.rn.bf16x2.f32 %0, %1, %2;" : "=r"(r) : "f"(hi), "f"(lo));
    return r;
}
__device__ __forceinline__ u32 cvt_f16x2(float hi, float lo) {
    u32 r;
    asm("cvt.rn.f16x2.f32 %0, %1, %2;" : "=r"(r) : "f"(hi), "f"(lo));
    return r;
}
__device__ __forceinline__ u32 ex2_f16x2(u32 t) {
    u32 r;
    asm("ex2.approx.f16x2 %0, %1;" : "=r"(r) : "r"(t));
    return r;
}
__device__ __forceinline__ float bf16bits_f(u16 v) {
    return __uint_as_float(((u32)v) << 16);
}
__device__ __forceinline__ void split2(float a, float b, u32& h, u32& l) {
    h = cvt_bf16x2(b, a);
    float la = a - bf16bits_f((u16)h);
    float lb = b - bf16bits_f((u16)(h >> 16));
    l = cvt_bf16x2(lb, la);
}

#define LDSM4(R, a) \
    asm volatile("ldmatrix.sync.aligned.m8n8.x4.shared.b16 {%0,%1,%2,%3}, [%4];" \
        : "=r"((R)[0]), "=r"((R)[1]), "=r"((R)[2]), "=r"((R)[3]) : "r"(a))
#define LDSM4T(R, a) \
    asm volatile("ldmatrix.sync.aligned.m8n8.x4.trans.shared.b16 {%0,%1,%2,%3}, [%4];" \
        : "=r"((R)[0]), "=r"((R)[1]), "=r"((R)[2]), "=r"((R)[3]) : "r"(a))

#define MMA(C, A, b0, b1) \
    asm volatile("mma.sync.aligned.m16n8k16.row.col.f32.bf16.bf16.f32 " \
        "{%0,%1,%2,%3}, {%4,%5,%6,%7}, {%8,%9}, {%0,%1,%2,%3};" \
        : "+f"((C)[0]), "+f"((C)[1]), "+f"((C)[2]), "+f"((C)[3]) \
        : "r"((A)[0]), "r"((A)[1]), "r"((A)[2]), "r"((A)[3]), "r"(b0), "r"(b1))

#define MMAH(C, A, b0, b1) \
    asm volatile("mma.sync.aligned.m16n8k16.row.col.f32.f16.f16.f32 " \
        "{%0,%1,%2,%3}, {%4,%5,%6,%7}, {%8,%9}, {%0,%1,%2,%3};" \
        : "+f"((C)[0]), "+f"((C)[1]), "+f"((C)[2]), "+f"((C)[3]) \
        : "r"((A)[0]), "r"((A)[1]), "r"((A)[2]), "r"((A)[3]), "r"(b0), "r"(b1))

#define WTR 40
#define XTR 72

// ---------------- projections -----------------------------------------------
// NOUT==2: z = b*3+s, computes K,V for that (b,s), sharing one X tile/B-frags.
// NOUT==1: z = b, computes Q from stream 0.
template<int NOUT>
__global__ __launch_bounds__(128)
void proj_f16(const float* __restrict__ Wa_, const float* __restrict__ ba_,
              const float* __restrict__ Wb_, const float* __restrict__ bb_,
              const float* __restrict__ x0,
              const float* __restrict__ x1,
              const float* __restrict__ x2,
              const float* __restrict__ g0p,
              const float* __restrict__ g1p,
              const float* __restrict__ g2p,
              u16* __restrict__ Ya,
              u16* __restrict__ Yb)
{
    __shared__ __align__(16) u16 sWa[64 * WTR];
    __shared__ __align__(16) u16 sWb[(NOUT == 2) ? 64 * WTR : 8];
    __shared__ __align__(16) u16 sX[32 * XTR];

    int b, s;
    if (NOUT == 2) { b = blockIdx.z / 3; s = blockIdx.z - b * 3; }
    else           { b = blockIdx.z; s = 0; }

    const float* xb = (s == 0) ? x0 : ((s == 1) ? x1 : x2);
    const float* gp = (s == 0) ? g0p : ((s == 1) ? g1p : g2p);
    const float gamma = gp[0];
    const float* X = xb + (size_t)b * CC * NN;

    const int o0 = blockIdx.y * 64;
    const int n0 = blockIdx.x * 64;
    const int tid  = threadIdx.x;
    const int w    = tid >> 5;
    const int lane = tid & 31;
    const int lr   = lane & 7;
    const int oct  = lane >> 3;
    const int g    = lane >> 2;
    const int t4   = lane & 3;

    const u32 bWa = smem_u32(sWa), bWb = smem_u32(sWb);
    const u32 bX  = smem_u32(sX);

    int wm[4], wk[4], xk[4], xn[4];
    #pragma unroll
    for (int j = 0; j < 4; j++) {
        int i = tid + j * 128;
        wm[j] = i >> 3;  wk[j] = (i & 7) * 4;
        xk[j] = i >> 4;  xn[j] = (i & 15) * 4;
    }

    // register prefetch of first k-tile
    float4 war[4], wbr[4], xr[4];
    #pragma unroll
    for (int j = 0; j < 4; j++) {
        war[j] = *(const float4*)&Wa_[(size_t)(o0 + wm[j]) * CC + wk[j]];
        if (NOUT == 2)
            wbr[j] = *(const float4*)&Wb_[(size_t)(o0 + wm[j]) * CC + wk[j]];
        xr[j] = *(const float4*)&X[(size_t)xk[j] * NN + n0 + xn[j]];
    }

    float CA[8][4] = {};
    float CB[(NOUT == 2) ? 8 : 1][4] = {};

    for (int kb = 0; kb < CC; kb += 32) {
        if (kb) __syncthreads();
        #pragma unroll
        for (int j = 0; j < 4; j++) {
            *(uint2*)&sWa[wm[j] * WTR + wk[j]] =
                make_uint2(cvt_f16x2(war[j].y, war[j].x), cvt_f16x2(war[j].w, war[j].z));
            if (NOUT == 2)
                *(uint2*)&sWb[wm[j] * WTR + wk[j]] =
                    make_uint2(cvt_f16x2(wbr[j].y, wbr[j].x), cvt_f16x2(wbr[j].w, wbr[j].z));
            float4 xv = xr[j];
            xv.x *= gamma; xv.y *= gamma; xv.z *= gamma; xv.w *= gamma;
            *(uint2*)&sX[xk[j] * XTR + xn[j]] =
                make_uint2(cvt_f16x2(xv.y, xv.x), cvt_f16x2(xv.w, xv.z));
        }
        __syncthreads();

        if (kb + 32 < CC) {
            #pragma unroll
            for (int j = 0; j < 4; j++) {
                war[j] = *(const float4*)&Wa_[(size_t)(o0 + wm[j]) * CC + kb + 32 + wk[j]];
                if (NOUT == 2)
                    wbr[j] = *(const float4*)&Wb_[(size_t)(o0 + wm[j]) * CC + kb + 32 + wk[j]];
                xr[j] = *(const float4*)&X[(size_t)(kb + 32 + xk[j]) * NN + n0 + xn[j]];
            }
        }

        #pragma unroll
        for (int kt = 0; kt < 2; kt++) {
            u32 aoff = (u32)(((w * 16 + (oct & 1) * 8 + lr) * WTR + kt * 16 + (oct >> 1) * 8) * 2);
            u32 aa[4], ab[4];
            LDSM4(aa, bWa + aoff);
            if (NOUT == 2) LDSM4(ab, bWb + aoff);
            #pragma unroll
            for (int nt = 0; nt < 4; nt++) {
                u32 boff = (u32)(((kt * 16 + (oct & 1) * 8 + lr) * XTR + nt * 16 + (oct >> 1) * 8) * 2);
                u32 bx[4];
                LDSM4T(bx, bX + boff);
                MMAH(CA[2 * nt],     aa, bx[0], bx[1]);
                MMAH(CA[2 * nt + 1], aa, bx[2], bx[3]);
                if (NOUT == 2) {
                    MMAH(CB[2 * nt],     ab, bx[0], bx[1]);
                    MMAH(CB[2 * nt + 1], ab, bx[2], bx[3]);
                }
            }
        }
    }

    const int or0 = o0 + w * 16 + g;
    const int or1 = or0 + 8;
    const float a0 = ba_[or0], a1 = ba_[or1];
    float b0v = 0.0f, b1v = 0.0f;
    if (NOUT == 2) { b0v = bb_[or0]; b1v = bb_[or1]; }
    const size_t ybase = (NOUT == 2) ? (size_t)((b * 3 + s) * CC) * NN
                                     : (size_t)(b * CC) * NN;
    #pragma unroll
    for (int j = 0; j < 8; j++) {
        int ne = n0 + (j >> 1) * 16 + (j & 1) * 8 + 2 * t4;
        size_t i0 = ybase + (size_t)or0 * NN + ne;
        size_t i1 = ybase + (size_t)or1 * NN + ne;
        *(u32*)(Ya + i0) = cvt_f16x2(CA[j][1] + a0, CA[j][0] + a0);
        *(u32*)(Ya + i1) = cvt_f16x2(CA[j][3] + a1, CA[j][2] + a1);
        if (NOUT == 2) {
            *(u32*)(Yb + i0) = cvt_f16x2(CB[j][1] + b0v, CB[j][0] + b0v);
            *(u32*)(Yb + i1) = cvt_f16x2(CB[j][3] + b1v, CB[j][2] + b1v);
        }
    }
}

// ---------------- combine: 3 stream partials -> normalized bf16 hi/lo ------
__global__ __launch_bounds__(256)
void combine_kernel()
{
    const int nvec = NN / 4;
    int t = blockIdx.x * 256 + threadIdx.x;      // over BB*CC*nvec
    int n0 = (t % nvec) * 4;
    int c  = (t / nvec) % CC;
    int b  = t / (nvec * CC);
    int h  = c / DK;

    size_t eo = ((size_t)(b * 3) * CC + c) * NN + n0;
    float4 p0 = *(const float4*)&g_part[eo];
    float4 p1 = *(const float4*)&g_part[eo + (size_t)CC * NN];
    float4 p2 = *(const float4*)&g_part[eo + (size_t)2 * CC * NN];
    size_t so = ((size_t)(b * 3) * NHEAD + h) * NN + n0;
    float4 s0 = *(const float4*)&g_ssum[so];
    float4 s1 = *(const float4*)&g_ssum[so + (size_t)NHEAD * NN];
    float4 s2 = *(const float4*)&g_ssum[so + (size_t)2 * NHEAD * NN];

    float4 xv;
    xv.x = __fdividef(p0.x + p1.x + p2.x, s0.x + s1.x + s2.x);
    xv.y = __fdividef(p0.y + p1.y + p2.y, s0.y + s1.y + s2.y);
    xv.z = __fdividef(p0.z + p1.z + p2.z, s0.z + s1.z + s2.z);
    xv.w = __fdividef(p0.w + p1.w + p2.w, s0.w + s1.w + s2.w);

    u32 h01, l01, h23, l23;
    split2(xv.x, xv.y, h01, l01);
    split2(xv.z, xv.w, h23, l23);
    size_t di = ((size_t)b * CC + c) * NN + n0;
    *(uint2*)(g_Xh + di) = make_uint2(h01, h23);
    *(uint2*)(g_Xl + di) = make_uint2(l01, l23);
}

// ---------------- Wo projection: 64o x 32n tiles (grid 512) ----------------
#define XTR2 40

__global__ __launch_bounds__(128)
void proj_wo(const float* __restrict__ Wm,
             const float* __restrict__ bias,
             float* __restrict__ Yf)
{
    __shared__ __align__(16) u16 sWh[64 * WTR], sWl[64 * WTR];
    __shared__ __align__(16) u16 sXh[32 * XTR2], sXl[32 * XTR2];

    const int b  = blockIdx.z;
    const int o0 = blockIdx.y * 64;
    const int n0 = blockIdx.x * 32;
    const int tid  = threadIdx.x;
    const int w    = tid >> 5;
    const int lane = tid & 31;
    const int lr   = lane & 7;
    const int oct  = lane >> 3;
    const int g    = lane >> 2;
    const int t4   = lane & 3;

    const u16* Xh = g_Xh + (size_t)b * CC * NN;
    const u16* Xl = g_Xl + (size_t)b * CC * NN;

    const u32 bWh = smem_u32(sWh), bWl = smem_u32(sWl);
    const u32 bXh = smem_u32(sXh), bXl = smem_u32(sXl);

    int wm[4], wk[4], xk[2], xn[2];
    #pragma unroll
    for (int j = 0; j < 4; j++) {
        int i = tid + j * 128;
        wm[j] = i >> 3;  wk[j] = (i & 7) * 4;
    }
    #pragma unroll
    for (int j = 0; j < 2; j++) {
        int i = tid + j * 128;
        xk[j] = i >> 3;  xn[j] = (i & 7) * 4;
    }

    float4 wr[4];
    uint2 xhr[2], xlr[2];
    #pragma unroll
    for (int j = 0; j < 4; j++)
        wr[j] = *(const float4*)&Wm[(size_t)(o0 + wm[j]) * CC + wk[j]];
    #pragma unroll
    for (int j = 0; j < 2; j++) {
        size_t xo = (size_t)xk[j] * NN + n0 + xn[j];
        xhr[j] = *(const uint2*)(Xh + xo);
        xlr[j] = *(const uint2*)(Xl + xo);
    }

    float Cacc[4][4] = {};

    for (int kb = 0; kb < CC; kb += 32) {
        if (kb) __syncthreads();
        #pragma unroll
        for (int j = 0; j < 4; j++) {
            u32 h01, l01, h23, l23;
            split2(wr[j].x, wr[j].y, h01, l01);
            split2(wr[j].z, wr[j].w, h23, l23);
            *(uint2*)&sWh[wm[j] * WTR + wk[j]] = make_uint2(h01, h23);
            *(uint2*)&sWl[wm[j] * WTR + wk[j]] = make_uint2(l01, l23);
        }
        #pragma unroll
        for (int j = 0; j < 2; j++) {
            *(uint2*)&sXh[xk[j] * XTR2 + xn[j]] = xhr[j];
            *(uint2*)&sXl[xk[j] * XTR2 + xn[j]] = xlr[j];
        }
        __syncthreads();

        if (kb + 32 < CC) {
            #pragma unroll
            for (int j = 0; j < 4; j++)
                wr[j] = *(const float4*)&Wm[(size_t)(o0 + wm[j]) * CC + kb + 32 + wk[j]];
            #pragma unroll
            for (int j = 0; j < 2; j++) {
                size_t xo = (size_t)(kb + 32 + xk[j]) * NN + n0 + xn[j];
                xhr[j] = *(const uint2*)(Xh + xo);
                xlr[j] = *(const uint2*)(Xl + xo);
            }
        }

        #pragma unroll
        for (int kt = 0; kt < 2; kt++) {
            u32 ah[4], al[4];
            u32 aoff = (u32)(((w * 16 + (oct & 1) * 8 + lr) * WTR + kt * 16 + (oct >> 1) * 8) * 2);
            LDSM4(ah, bWh + aoff);
            LDSM4(al, bWl + aoff);
            #pragma unroll
            for (int nt = 0; nt < 2; nt++) {
                u32 boff = (u32)(((kt * 16 + (oct & 1) * 8 + lr) * XTR2 + nt * 16 + (oct >> 1) * 8) * 2);
                u32 bh[4], bl[4];
                LDSM4T(bh, bXh + boff);
                LDSM4T(bl, bXl + boff);
                MMA(Cacc[2 * nt],     ah, bh[0], bh[1]);
                MMA(Cacc[2 * nt],     al, bh[0], bh[1]);
                MMA(Cacc[2 * nt],     ah, bl[0], bl[1]);
                MMA(Cacc[2 * nt + 1], ah, bh[2], bh[3]);
                MMA(Cacc[2 * nt + 1], al, bh[2], bh[3]);
                MMA(Cacc[2 * nt + 1], ah, bl[2], bl[3]);
            }
        }
    }

    const int or0 = o0 + w * 16 + g;
    const int or1 = or0 + 8;
    const float bv0 = bias[or0], bv1 = bias[or1];
    #pragma unroll
    for (int j = 0; j < 4; j++) {
        int ne = n0 + (j >> 1) * 16 + (j & 1) * 8 + 2 * t4;
        size_t i0 = (size_t)(b * CC + or0) * NN + ne;
        size_t i1 = (size_t)(b * CC + or1) * NN + ne;
        *(float2*)&Yf[i0] = make_float2(Cacc[j][0] + bv0, Cacc[j][1] + bv0);
        *(float2*)&Yf[i1] = make_float2(Cacc[j][2] + bv1, Cacc[j][3] + bv1);
    }
}

// ---------------- mma.sync attention: split-KV, ex2.f16x2, ones-col ssum ---
#define TROW 72
#define VROWS 48        // 32 data rows + ones row (32) + zero rows (33..47)

__global__ __launch_bounds__(128, 5)
void attn_mma_kernel()
{
    __shared__ __align__(16) u16 sQ[DK * TROW];
    __shared__ __align__(16) u16 sK[2][DK * TROW];
    __shared__ __align__(16) u16 sV[2][VROWS * TROW];

    const int tid  = threadIdx.x;
    const int w    = tid >> 5;
    const int lane = tid & 31;
    const int lr   = lane & 7;
    const int oct  = lane >> 3;
    const int g    = lane >> 2;
    const int t4   = lane & 3;

    const int bz = blockIdx.z;      // 0..11
    const int b  = bz / 3;
    const int s  = bz - b * 3;      // stream
    const int hh = blockIdx.y;
    const int q0 = blockIdx.x * 64;
    const int qw = w * 16;

    const size_t kvbase = ((size_t)(b * 3 + s) * CC + hh * DK) * NN;
    const u16* Kg = g_K16 + kvbase;
    const u16* Vg = g_V16 + kvbase;

    int prow[2], pcol[2];
    #pragma unroll
    for (int j = 0; j < 2; j++) {
        int i = tid + j * 128;
        prow[j] = i >> 3;
        pcol[j] = (i & 7) * 8;
    }

    // init V rows 32..47 (row 32 = 1.0h for the ssum column, rest 0), both bufs
    for (int i = tid; i < 16 * TROW; i += 128) {
        int r = 32 + i / TROW;
        int cp = i % TROW;
        u16 val = (r == 32) ? (u16)0x3C00 : (u16)0;
        sV[0][r * TROW + cp] = val;
        sV[1][r * TROW + cp] = val;
    }

    // chunk 0 -> buf0 (direct), prefetch chunk 1 into regs
    uint4 pK[2], pV[2];
    #pragma unroll
    for (int j = 0; j < 2; j++) {
        size_t go = (size_t)prow[j] * NN + pcol[j];
        uint4 k0 = *(const uint4*)&Kg[go];
        uint4 v0 = *(const uint4*)&Vg[go];
        u32 so = prow[j] * TROW + pcol[j];
        *(uint4*)&sK[0][so] = k0;
        *(uint4*)&sV[0][so] = v0;
        pK[j] = *(const uint4*)&Kg[go + SK];
        pV[j] = *(const uint4*)&Vg[go + SK];
    }
    // Q tile
    {
        const u16* srcQ = g_Q16 + ((size_t)b * CC + hh * DK) * NN + q0;
        #pragma unroll
        for (int j = 0; j < 2; j++) {
            size_t go = (size_t)prow[j] * NN + pcol[j];
            *(uint4*)&sQ[prow[j] * TROW + pcol[j]] = *(const uint4*)&srcQ[go];
        }
    }
    __syncthreads();

    u32 qa[2][4];
    {
        const u32 dOff = (oct >> 1) * 8;
        const u32 qOff = (oct & 1) * 8;
        #pragma unroll
        for (int kt = 0; kt < 2; kt++) {
            u32 off = (u32)(((kt * 16 + dOff + lr) * TROW + qw + qOff) * 2);
            LDSM4T(qa[kt], smem_u32(sQ) + off);
        }
    }

    float Ofr[5][4] = {};   // [4] = ones-column ntile: ssum in fp32, MMA-reduced
    const float SC2 = 0.25503483f;   // log2(e) / sqrt(32)

    for (int chunk = 0; chunk < CPS; chunk++) {
        const int cur = chunk & 1;
        const u32 baseK = smem_u32(sK[cur]);
        const u32 baseV = smem_u32(sV[cur]);

        // stage next chunk into the other buffer (overlaps with MMAs below)
        if (chunk + 1 < CPS) {
            #pragma unroll
            for (int j = 0; j < 2; j++) {
                u32 so = prow[j] * TROW + pcol[j];
                *(uint4*)&sK[cur ^ 1][so] = pK[j];
                *(uint4*)&sV[cur ^ 1][so] = pV[j];
            }
        }
        if (chunk + 2 < CPS) {
            const int k2 = (chunk + 2) * SK;
            #pragma unroll
            for (int j = 0; j < 2; j++) {
                size_t go = (size_t)prow[j] * NN + k2 + pcol[j];
                pK[j] = *(const uint4*)&Kg[go];
                pV[j] = *(const uint4*)&Vg[go];
            }
        }

        // ---- S = Q K^T (single fp16) ----
        float S[8][4] = {};
        {
            const u32 dOff   = (oct & 1) * 8;
            const u32 keyOff = (oct >> 1) * 8;
            #pragma unroll
            for (int np = 0; np < 4; np++) {
                #pragma unroll
                for (int kt = 0; kt < 2; kt++) {
                    u32 off = (u32)(((kt * 16 + dOff + lr) * TROW + np * 16 + keyOff) * 2);
                    u32 bv[4];
                    LDSM4T(bv, baseK + off);
                    MMAH(S[2 * np],     qa[kt], bv[0], bv[1]);
                    MMAH(S[2 * np + 1], qa[kt], bv[2], bv[3]);
                }
            }
        }

        // ---- softmax: p = 2^(s*SC2), ex2.approx.f16x2, zero shift ----
        u32 pa[4][4];
        #pragma unroll
        for (int nt = 0; nt < 8; nt++) {
            float t0 = S[nt][0] * SC2;
            float t1 = S[nt][1] * SC2;
            float t2 = S[nt][2] * SC2;
            float t3 = S[nt][3] * SC2;
            int kt = nt >> 1;
            int r  = (nt & 1) * 2;
            pa[kt][r]     = ex2_f16x2(cvt_f16x2(t1, t0));
            pa[kt][r + 1] = ex2_f16x2(cvt_f16x2(t3, t2));
        }

        // ---- O += P V ; ssum via ones column (d=32) ----
        {
            const u32 dOff   = (oct >> 1) * 8;
            const u32 keyOff = (oct & 1) * 8;
            #pragma unroll
            for (int kt = 0; kt < 4; kt++) {
                #pragma unroll
                for (int dp = 0; dp < 2; dp++) {
                    u32 off = (u32)(((dp * 16 + dOff + lr) * TROW + kt * 16 + keyOff) * 2);
                    u32 vv[4];
                    LDSM4(vv, baseV + off);
                    MMAH(Ofr[2 * dp],     pa[kt], vv[0], vv[1]);
                    MMAH(Ofr[2 * dp + 1], pa[kt], vv[2], vv[3]);
                }
                u32 off1 = (u32)(((32 + dOff + lr) * TROW + kt * 16 + keyOff) * 2);
                u32 vv1[4];
                LDSM4(vv1, baseV + off1);
                MMAH(Ofr[4], pa[kt], vv1[0], vv1[1]);
            }
        }
        __syncthreads();   // all reads of buf[cur] done; buf[cur^1] stores visible
    }

    // ---- store unnormalized partials + exact MMA-reduced softmax sums ----
    const size_t obase = kvbase;
    const int qg = q0 + qw + g;
    #pragma unroll
    for (int nt = 0; nt < 4; nt++) {
        int d0 = nt * 8 + 2 * t4;
        g_part[obase + (size_t)d0 * NN + qg]           = Ofr[nt][0];
        g_part[obase + (size_t)(d0 + 1) * NN + qg]     = Ofr[nt][1];
        g_part[obase + (size_t)d0 * NN + qg + 8]       = Ofr[nt][2];
        g_part[obase + (size_t)(d0 + 1) * NN + qg + 8] = Ofr[nt][3];
    }
    if (t4 == 0) {
        size_t sb = ((size_t)(b * 3 + s) * NHEAD + hh) * NN;
        g_ssum[sb + qg]     = Ofr[4][0];   // col 32 (ones) = row sum, row qg
        g_ssum[sb + qg + 8] = Ofr[4][2];   // row qg+8
    }
}

// ---------------- launch --------------------------------------------------
extern "C" void kernel_launch(void* const* d_in, const int* in_sizes, int n_in,
                              void* d_out, int out_size)
{
    const float* x0 = (const float*)d_in[0];
    const float* x1 = (const float*)d_in[1];
    const float* x2 = (const float*)d_in[2];
    const float* g0 = (const float*)d_in[3];
    const float* g1 = (const float*)d_in[4];
    const float* g2 = (const float*)d_in[5];
    const float* Wq = (const float*)d_in[6];
    const float* bq = (const float*)d_in[7];
    const float* Wk = (const float*)d_in[8];
    const float* bk = (const float*)d_in[9];
    const float* Wv = (const float*)d_in[10];
    const float* bv = (const float*)d_in[11];
    const float* Wo = (const float*)d_in[12];
    const float* bo = (const float*)d_in[13];
    float* out = (float*)d_out;

    u16 *Q16, *K16, *V16;
    cudaGetSymbolAddress((void**)&Q16, g_Q16);
    cudaGetSymbolAddress((void**)&K16, g_K16);
    cudaGetSymbolAddress((void**)&V16, g_V16);

    dim3 blk(128);

    // K+V per (b,s): 2 accumulator sets, shared X tile + B-frags (768 blocks)
    dim3 gridKV(NN / 64, CC / 64, BB * 3);
    proj_f16<2><<<gridKV, blk>>>(Wk, bk, Wv, bv, x0, x1, x2, g0, g1, g2,
                                 K16, V16);
    // Q from stream 0: 1 accumulator set (256 blocks)
    dim3 gridQ(NN / 64, CC / 64, BB);
    proj_f16<1><<<gridQ, blk>>>(Wq, bq, nullptr, nullptr, x0, x1, x2,
                                g0, g1, g2, Q16, nullptr);

    dim3 agrid(NN / 64, NHEAD, BB * 3);
    attn_mma_kernel<<<agrid, blk>>>();

    // combine 3 stream partials -> normalized attn out as bf16 hi/lo
    combine_kernel<<<BB * CC * (NN / 4) / 256, 256>>>();

    // final projection: 64x32 tiles, grid 512
    dim3 gridWo(NN / 32, CC / 64, BB);
    proj_wo<<<gridWo, blk>>>(Wo, bo, out);
}